// round 2
// baseline (speedup 1.0000x reference)
#include <cuda_runtime.h>
#include <math.h>

// ---------------- problem constants ----------------
#define BATCH   2
#define SEQLEN  2048
#define DMODEL  1024
#define ED      2048
#define NST     16
#define DTR     64
#define DCONV   4
#define ROWS    (BATCH*SEQLEN)      // 4096
#define DBCW    (DTR + 2*NST)       // 96
#define NCH     16
#define CH      (SEQLEN/NCH)        // 128

// ---------------- scratch (static device arrays; no allocation) ----------------
__device__ float g_xz   [(size_t)ROWS * 2 * ED];     // 64 MB : [row][0..2047]=xc_raw, [2048..4095]=z
__device__ float g_xc   [(size_t)ROWS * ED];         // 32 MB : conv+silu output
__device__ float g_dbc  [(size_t)ROWS * DBCW];       // 1.5 MB: [delta_r(64) | B(16) | C(16)]
__device__ float g_delta[(size_t)ROWS * ED];         // 32 MB
__device__ float g_yz   [(size_t)ROWS * ED];         // 32 MB
__device__ float g_aprod[(size_t)BATCH * ED * NCH * NST];  // 4 MB
__device__ float g_hend [(size_t)BATCH * ED * NCH * NST];  // 4 MB
__device__ float g_h0   [(size_t)BATCH * ED * NCH * NST];  // 4 MB

// ---------------- helpers ----------------
__device__ __forceinline__ float ex2f(float x) {
    float y; asm("ex2.approx.f32 %0, %1;" : "=f"(y) : "f"(x)); return y;
}
__device__ __forceinline__ float siluf(float x) {
    // x * sigmoid(x) = x / (1 + exp(-x))
    return x / (1.f + ex2f(-1.4426950408889634f * x));
}
__device__ __forceinline__ float softplusf(float x) {
    return (x > 20.f) ? x : log1pf(__expf(x));
}

// ---------------- generic tiled SGEMM:  C[M,N] = A[M,K] @ B[N,K]^T ----------------
// BM=BN=128, BK=16, 256 threads, 8x8 per thread.
// Requires M%128==0, K%16==0 (true for all call sites). N guarded.
// ATOMIC=1: accumulate into C with atomicAdd (split-K via blockIdx.z / kSlice).
// EPI=1: C = softplus(acc + bias[n])
template<int EPI, int ATOMIC>
__global__ void __launch_bounds__(256, 2)
sgemm_nt(const float* __restrict__ A, const float* __restrict__ B,
         float* __restrict__ C, const float* __restrict__ bias,
         int M, int N, int K, int lda, int ldb, int ldc, int kSlice)
{
    __shared__ float As[16][128];
    __shared__ float Bs[16][128];

    const int t  = threadIdx.x;
    const int tx = t & 15;          // 0..15 -> 8 cols each
    const int ty = t >> 4;          // 0..15 -> 8 rows each
    const int mBlk = blockIdx.y * 128;
    const int nBlk = blockIdx.x * 128;
    const int kBeg = blockIdx.z * kSlice;
    const int kEnd = min(K, kBeg + kSlice);

    float acc[8][8];
#pragma unroll
    for (int i = 0; i < 8; i++)
#pragma unroll
        for (int j = 0; j < 8; j++) acc[i][j] = 0.f;

    for (int k0 = kBeg; k0 < kEnd; k0 += 16) {
#pragma unroll
        for (int i = 0; i < 2; i++) {
            int v   = t + i * 256;      // 0..511
            int row = v >> 2;           // 0..127
            int k4  = (v & 3) * 4;      // 0,4,8,12
            float4 a = *(const float4*)&A[(size_t)(mBlk + row) * lda + k0 + k4];
            As[k4 + 0][row] = a.x; As[k4 + 1][row] = a.y;
            As[k4 + 2][row] = a.z; As[k4 + 3][row] = a.w;
            float4 bv = make_float4(0.f, 0.f, 0.f, 0.f);
            if (nBlk + row < N)
                bv = *(const float4*)&B[(size_t)(nBlk + row) * ldb + k0 + k4];
            Bs[k4 + 0][row] = bv.x; Bs[k4 + 1][row] = bv.y;
            Bs[k4 + 2][row] = bv.z; Bs[k4 + 3][row] = bv.w;
        }
        __syncthreads();

#pragma unroll
        for (int kk = 0; kk < 16; kk++) {
            float ra[8], rb[8];
            *(float4*)&ra[0] = *(const float4*)&As[kk][ty * 8];
            *(float4*)&ra[4] = *(const float4*)&As[kk][ty * 8 + 4];
            *(float4*)&rb[0] = *(const float4*)&Bs[kk][tx * 8];
            *(float4*)&rb[4] = *(const float4*)&Bs[kk][tx * 8 + 4];
#pragma unroll
            for (int i = 0; i < 8; i++)
#pragma unroll
                for (int j = 0; j < 8; j++)
                    acc[i][j] = fmaf(ra[i], rb[j], acc[i][j]);
        }
        __syncthreads();
    }

#pragma unroll
    for (int i = 0; i < 8; i++) {
        int m = mBlk + ty * 8 + i;
#pragma unroll
        for (int j = 0; j < 8; j++) {
            int n = nBlk + tx * 8 + j;
            if (n < N) {
                float v = acc[i][j];
                if (ATOMIC) {
                    atomicAdd(&C[(size_t)m * ldc + n], v);
                } else {
                    if (EPI == 1) { v += bias[n]; v = softplusf(v); }
                    C[(size_t)m * ldc + n] = v;
                }
            }
        }
    }
}

// ---------------- depthwise causal conv1d + silu ----------------
__global__ void conv_silu_kernel(const float* __restrict__ conv_w,
                                 const float* __restrict__ conv_b)
{
    int idx = blockIdx.x * blockDim.x + threadIdx.x;   // over ROWS*ED
    int ed = idx & (ED - 1);
    int r  = idx >> 11;             // row = b*SEQLEN + l
    int b  = r >> 11;
    int l  = r & (SEQLEN - 1);
    float acc = conv_b[ed];
#pragma unroll
    for (int k = 0; k < DCONV; k++) {
        int ls = l - (DCONV - 1) + k;
        if (ls >= 0)
            acc = fmaf(conv_w[ed * DCONV + k],
                       g_xz[(size_t)(b * SEQLEN + ls) * (2 * ED) + ed], acc);
    }
    g_xc[(size_t)idx] = siluf(acc);
}

__global__ void zero_kernel(float* __restrict__ p, int n)
{
    int i = blockIdx.x * blockDim.x + threadIdx.x;
    if (i < n) p[i] = 0.f;
}

// ---------------- chunked selective scan ----------------
// phase 1: per (b, ed, chunk): local scan with h0=0 -> h_end, chunk decay = exp(A * sum(delta))
__global__ void scan_phase1(const float* __restrict__ A_log)
{
    int idx = blockIdx.x * blockDim.x + threadIdx.x;   // [0, BATCH*NCH*ED)
    int ed = idx & (ED - 1);
    int c  = (idx >> 11) & (NCH - 1);
    int b  = idx >> 15;

    float A2[NST];
#pragma unroll
    for (int n = 0; n < NST; n++)
        A2[n] = -__expf(A_log[ed * NST + n]) * 1.4426950408889634f;  // A * log2(e)

    float h[NST];
#pragma unroll
    for (int n = 0; n < NST; n++) h[n] = 0.f;
    float sd = 0.f;

    int row0 = b * SEQLEN + c * CH;
    const float* dl = g_delta + (size_t)row0 * ED + ed;
    const float* xv = g_xc    + (size_t)row0 * ED + ed;

    for (int l = 0; l < CH; l++) {
        float d = dl[(size_t)l * ED];
        float x = xv[(size_t)l * ED];
        sd += d;
        float dx = d * x;
        const float4* bb = (const float4*)(g_dbc + (size_t)(row0 + l) * DBCW + DTR);
#pragma unroll
        for (int q = 0; q < 4; q++) {
            float4 bv = bb[q];
            float bw[4] = { bv.x, bv.y, bv.z, bv.w };
#pragma unroll
            for (int j = 0; j < 4; j++) {
                int n = q * 4 + j;
                float dA = ex2f(A2[n] * d);
                h[n] = fmaf(dA, h[n], bw[j] * dx);
            }
        }
    }

    size_t ob = ((size_t)(b * ED + ed) * NCH + c) * NST;
#pragma unroll
    for (int n = 0; n < NST; n++) {
        g_hend [ob + n] = h[n];
        g_aprod[ob + n] = ex2f(A2[n] * sd);
    }
}

// phase 2: sequential cross-chunk recurrence (tiny)
__global__ void scan_phase2()
{
    int tid = blockIdx.x * blockDim.x + threadIdx.x;   // BATCH*ED*NST
    int n = tid & (NST - 1);
    int e = tid >> 4;                                  // b*ED + ed
    float h = 0.f;
#pragma unroll
    for (int c = 0; c < NCH; c++) {
        size_t idx = ((size_t)e * NCH + c) * NST + n;
        g_h0[idx] = h;
        h = fmaf(g_aprod[idx], h, g_hend[idx]);
    }
}

// phase 3: replay with correct h0; fuse y = sum_n h*C + D*xc and yz = y*silu(z)
__global__ void scan_phase3(const float* __restrict__ A_log,
                            const float* __restrict__ D_param)
{
    int idx = blockIdx.x * blockDim.x + threadIdx.x;
    int ed = idx & (ED - 1);
    int c  = (idx >> 11) & (NCH - 1);
    int b  = idx >> 15;

    float A2[NST];
#pragma unroll
    for (int n = 0; n < NST; n++)
        A2[n] = -__expf(A_log[ed * NST + n]) * 1.4426950408889634f;

    size_t hb = ((size_t)(b * ED + ed) * NCH + c) * NST;
    float h[NST];
#pragma unroll
    for (int n = 0; n < NST; n++) h[n] = g_h0[hb + n];
    float Dv = D_param[ed];

    int row0 = b * SEQLEN + c * CH;
    const float* dl = g_delta + (size_t)row0 * ED + ed;
    const float* xv = g_xc    + (size_t)row0 * ED + ed;

    for (int l = 0; l < CH; l++) {
        float d = dl[(size_t)l * ED];
        float x = xv[(size_t)l * ED];
        float dx = d * x;
        float y = Dv * x;
        const float4* bb = (const float4*)(g_dbc + (size_t)(row0 + l) * DBCW + DTR);
        const float4* cc = (const float4*)(g_dbc + (size_t)(row0 + l) * DBCW + DTR + NST);
#pragma unroll
        for (int q = 0; q < 4; q++) {
            float4 bv = bb[q];
            float4 cv = cc[q];
            float bw[4] = { bv.x, bv.y, bv.z, bv.w };
            float cw[4] = { cv.x, cv.y, cv.z, cv.w };
#pragma unroll
            for (int j = 0; j < 4; j++) {
                int n = q * 4 + j;
                float dA = ex2f(A2[n] * d);
                h[n] = fmaf(dA, h[n], bw[j] * dx);
                y = fmaf(h[n], cw[j], y);
            }
        }
        float z = g_xz[(size_t)(row0 + l) * (2 * ED) + ED + ed];
        g_yz[(size_t)(row0 + l) * ED + ed] = y * siluf(z);
    }
}

// ---------------- launch ----------------
extern "C" void kernel_launch(void* const* d_in, const int* in_sizes, int n_in,
                              void* d_out, int out_size)
{
    const float* x         = (const float*)d_in[0];
    const float* in_proj_w = (const float*)d_in[1];
    const float* conv_w    = (const float*)d_in[2];
    const float* conv_b    = (const float*)d_in[3];
    const float* x_proj_w  = (const float*)d_in[4];
    const float* dt_w      = (const float*)d_in[5];
    const float* dt_b      = (const float*)d_in[6];
    const float* A_log     = (const float*)d_in[7];
    const float* D_param   = (const float*)d_in[8];
    float* out = (float*)d_out;

    float *p_xz, *p_xc, *p_dbc, *p_delta, *p_yz;
    cudaGetSymbolAddress((void**)&p_xz,    g_xz);
    cudaGetSymbolAddress((void**)&p_xc,    g_xc);
    cudaGetSymbolAddress((void**)&p_dbc,   g_dbc);
    cudaGetSymbolAddress((void**)&p_delta, g_delta);
    cudaGetSymbolAddress((void**)&p_yz,    g_yz);
    const float* out_proj_w = (const float*)d_in[9];

    // G1: xz = x @ in_proj_w^T   (4096 x 4096 x 1024)
    sgemm_nt<0, 0><<<dim3(4096 / 128, 4096 / 128, 1), 256>>>(
        x, in_proj_w, p_xz, nullptr, ROWS, 2 * ED, DMODEL,
        DMODEL, DMODEL, 2 * ED, DMODEL);

    // depthwise causal conv + silu
    conv_silu_kernel<<<(ROWS * ED) / 256, 256>>>(conv_w, conv_b);

    // G2: dbc = xc @ x_proj_w^T  (4096 x 96 x 2048), split-K=8 with atomics
    zero_kernel<<<(ROWS * DBCW + 255) / 256, 256>>>(p_dbc, ROWS * DBCW);
    sgemm_nt<0, 1><<<dim3(1, ROWS / 128, 8), 256>>>(
        p_xc, x_proj_w, p_dbc, nullptr, ROWS, DBCW, ED,
        ED, ED, DBCW, ED / 8);

    // G3: delta = softplus(dbc[:, :64] @ dt_w^T + dt_b)  (4096 x 2048 x 64)
    sgemm_nt<1, 0><<<dim3(ED / 128, ROWS / 128, 1), 256>>>(
        p_dbc, dt_w, p_delta, dt_b, ROWS, ED, DTR,
        DBCW, DTR, ED, DTR);

    // chunked selective scan
    scan_phase1<<<(BATCH * NCH * ED) / 128, 128>>>(A_log);
    scan_phase2<<<(BATCH * ED * NST) / 256, 256>>>();
    scan_phase3<<<(BATCH * NCH * ED) / 128, 128>>>(A_log, D_param);

    // G4: out = yz @ out_proj_w^T  (4096 x 1024 x 2048)
    sgemm_nt<0, 0><<<dim3(DMODEL / 128, ROWS / 128, 1), 256>>>(
        p_yz, out_proj_w, out, nullptr, ROWS, DMODEL, ED,
        ED, ED, DMODEL, ED);
}

// round 5
// speedup vs baseline: 2.3754x; 2.3754x over previous
#include <cuda_runtime.h>
#include <math.h>
#include <stdint.h>

// ---------------- problem constants ----------------
#define BATCH   2
#define SEQLEN  2048
#define DMODEL  1024
#define ED      2048
#define NST     16
#define DTR     64
#define DCONV   4
#define ROWS    (BATCH*SEQLEN)      // 4096
#define DBCW    (DTR + 2*NST)       // 96
#define NCH     16
#define CH      (SEQLEN/NCH)        // 128

// ---------------- scratch ----------------
__device__ float g_xz   [(size_t)ROWS * 2 * ED];
__device__ float g_xc   [(size_t)ROWS * ED];
__device__ float g_dbc  [(size_t)ROWS * DBCW];
__device__ float g_delta[(size_t)ROWS * ED];
__device__ float g_yz   [(size_t)ROWS * ED];
__device__ float g_aprod[(size_t)BATCH * ED * NCH * NST];
__device__ float g_hend [(size_t)BATCH * ED * NCH * NST];
__device__ float g_h0   [(size_t)BATCH * ED * NCH * NST];

// ---------------- math helpers ----------------
__device__ __forceinline__ float ex2f(float x) {
    float y; asm("ex2.approx.f32 %0, %1;" : "=f"(y) : "f"(x)); return y;
}
__device__ __forceinline__ float siluf(float x) {
    return x / (1.f + ex2f(-1.4426950408889634f * x));
}
__device__ __forceinline__ float softplusf(float x) {
    return (x > 20.f) ? x : log1pf(__expf(x));
}

// ---------------- PTX helpers (all plain sm_80+ features) ----------------
__device__ __forceinline__ uint32_t smem_u32(const void* p) {
    uint32_t a;
    asm("{ .reg .u64 t; cvta.to.shared.u64 t, %1; cvt.u32.u64 %0, t; }" : "=r"(a) : "l"(p));
    return a;
}
__device__ __forceinline__ void cp16(uint32_t dst, const void* src) {
    asm volatile("cp.async.cg.shared.global [%0], [%1], 16;" :: "r"(dst), "l"(src));
}
__device__ __forceinline__ void cp16z(uint32_t dst, const void* src, uint32_t sz) {
    asm volatile("cp.async.cg.shared.global [%0], [%1], 16, %2;" :: "r"(dst), "l"(src), "r"(sz));
}
__device__ __forceinline__ void cp_commit() {
    asm volatile("cp.async.commit_group;" ::: "memory");
}
template<int N> __device__ __forceinline__ void cp_wait() {
    asm volatile("cp.async.wait_group %0;" :: "n"(N) : "memory");
}
__device__ __forceinline__ uint32_t f2tf(float x) {
    uint32_t u; asm("cvt.rna.tf32.f32 %0, %1;" : "=r"(u) : "f"(x)); return u;
}
__device__ __forceinline__ void mma8(float* c, const uint32_t* a, const uint32_t* b) {
    asm volatile(
        "mma.sync.aligned.m16n8k8.row.col.f32.tf32.tf32.f32 "
        "{%0,%1,%2,%3}, {%4,%5,%6,%7}, {%8,%9}, {%0,%1,%2,%3};"
        : "+f"(c[0]), "+f"(c[1]), "+f"(c[2]), "+f"(c[3])
        : "r"(a[0]), "r"(a[1]), "r"(a[2]), "r"(a[3]), "r"(b[0]), "r"(b[1]));
}

// ---------------- tf32 mma.sync GEMM: C[M,N] = A[M,K] @ B[N,K]^T ----------------
// 128x128 CTA tile, 8 warps (2m x 4n), 64x32 warp tile, BK=16, 4-stage cp.async.
// Smem per stage: A 128x20 + B 128x20 floats (pad 4 -> conflict-free frags).
// EPI=1: C = softplus(acc + bias[n]).  ATOMIC=1: atomicAdd into C (split-K via z).
// GUARDN=1: N not multiple of 128; B tile rows >= N are zero-filled.
#define MM_STG_F   (128 * 20)            // floats per matrix per stage
#define MM_SMEM    (4 * 2 * MM_STG_F * 4)  // 81920 bytes

template<int EPI, int ATOMIC, int GUARDN>
__global__ void __launch_bounds__(256, 2)
gemm_mma(const float* __restrict__ A, const float* __restrict__ B,
         float* __restrict__ C, const float* __restrict__ bias,
         int M, int N, int K, int lda, int ldb, int ldc, int kSlice)
{
    extern __shared__ __align__(128) float sm[];
    const uint32_t sb = smem_u32(sm);
    const int tid  = threadIdx.x;
    const int lane = tid & 31;
    const int wid  = tid >> 5;
    const int wm   = wid >> 2;           // 0..1
    const int wn   = wid & 3;            // 0..3
    const int g    = lane >> 2;          // 0..7
    const int j    = lane & 3;           // 0..3
    const int mBlk = blockIdx.y * 128;
    const int nBlk = blockIdx.x * 128;
    const int kBeg = blockIdx.z * kSlice;
    const int T    = kSlice >> 4;

    float acc[4][4][4];
#pragma unroll
    for (int a = 0; a < 4; a++)
#pragma unroll
        for (int b = 0; b < 4; b++)
#pragma unroll
            for (int c = 0; c < 4; c++) acc[a][b][c] = 0.f;

    auto load_tile = [&](int kt, int s) {
        const int k0 = kBeg + kt * 16;
        const uint32_t aB = sb + (uint32_t)s * (2 * MM_STG_F * 4);
        const uint32_t bB = aB + MM_STG_F * 4;
#pragma unroll
        for (int i = 0; i < 2; i++) {
            int ch  = tid + i * 256;     // 0..511
            int row = ch >> 2;           // 0..127
            int c4  = ch & 3;            // chunk of 16B
            cp16(aB + row * 80 + c4 * 16,
                 A + (size_t)(mBlk + row) * lda + k0 + c4 * 4);
            if (GUARDN) {
                int brow = nBlk + row;
                int bcl  = min(brow, N - 1);
                uint32_t sz = (brow < N) ? 16u : 0u;
                cp16z(bB + row * 80 + c4 * 16,
                      B + (size_t)bcl * ldb + k0 + c4 * 4, sz);
            } else {
                cp16(bB + row * 80 + c4 * 16,
                     B + (size_t)(nBlk + row) * ldb + k0 + c4 * 4);
            }
        }
        cp_commit();
    };

    load_tile(0, 0);
    load_tile(1, 1);
    load_tile(2, 2);

    for (int kt = 0; kt < T; kt++) {
        cp_wait<2>();
        __syncthreads();

        if (kt + 3 < T) load_tile(kt + 3, (kt + 3) & 3);
        cp_commit();     // always commit (possibly empty) -> loop-invariant wait count

        const int buf = kt & 3;
        const float* As = sm + (size_t)buf * (2 * MM_STG_F);
        const float* Bs = As + MM_STG_F;

#pragma unroll
        for (int ks = 0; ks < 2; ks++) {
            const int k0 = ks * 8;
            uint32_t af[4][4], bf[4][2];
#pragma unroll
            for (int mt = 0; mt < 4; mt++) {
                int r = wm * 64 + mt * 16 + g;
                af[mt][0] = f2tf(As[r * 20 + k0 + j]);
                af[mt][1] = f2tf(As[(r + 8) * 20 + k0 + j]);
                af[mt][2] = f2tf(As[r * 20 + k0 + j + 4]);
                af[mt][3] = f2tf(As[(r + 8) * 20 + k0 + j + 4]);
            }
#pragma unroll
            for (int nt = 0; nt < 4; nt++) {
                int r = wn * 32 + nt * 8 + g;
                bf[nt][0] = f2tf(Bs[r * 20 + k0 + j]);
                bf[nt][1] = f2tf(Bs[r * 20 + k0 + j + 4]);
            }
#pragma unroll
            for (int mt = 0; mt < 4; mt++)
#pragma unroll
                for (int nt = 0; nt < 4; nt++)
                    mma8(acc[mt][nt], af[mt], bf[nt]);
        }
    }

    // epilogue
#pragma unroll
    for (int mt = 0; mt < 4; mt++) {
#pragma unroll
        for (int nt = 0; nt < 4; nt++) {
            int m = mBlk + wm * 64 + mt * 16 + g;
            int n = nBlk + wn * 32 + nt * 8 + 2 * j;
            float* cv = acc[mt][nt];
            if (GUARDN && n >= N) continue;
            float v0 = cv[0], v1 = cv[1], v2 = cv[2], v3 = cv[3];
            if (EPI == 1) {
                float b0 = bias[n], b1 = bias[n + 1];
                v0 = softplusf(v0 + b0); v1 = softplusf(v1 + b1);
                v2 = softplusf(v2 + b0); v3 = softplusf(v3 + b1);
            }
            if (ATOMIC) {
                atomicAdd(&C[(size_t)m * ldc + n],            v0);
                atomicAdd(&C[(size_t)m * ldc + n + 1],        v1);
                atomicAdd(&C[(size_t)(m + 8) * ldc + n],      v2);
                atomicAdd(&C[(size_t)(m + 8) * ldc + n + 1],  v3);
            } else {
                *(float2*)&C[(size_t)m * ldc + n]       = make_float2(v0, v1);
                *(float2*)&C[(size_t)(m + 8) * ldc + n] = make_float2(v2, v3);
            }
        }
    }
}

// ---------------- depthwise causal conv1d + silu ----------------
__global__ void conv_silu_kernel(const float* __restrict__ conv_w,
                                 const float* __restrict__ conv_b)
{
    int idx = blockIdx.x * blockDim.x + threadIdx.x;
    int ed = idx & (ED - 1);
    int r  = idx >> 11;
    int b  = r >> 11;
    int l  = r & (SEQLEN - 1);
    float acc = conv_b[ed];
#pragma unroll
    for (int k = 0; k < DCONV; k++) {
        int ls = l - (DCONV - 1) + k;
        if (ls >= 0)
            acc = fmaf(conv_w[ed * DCONV + k],
                       g_xz[(size_t)(b * SEQLEN + ls) * (2 * ED) + ed], acc);
    }
    g_xc[(size_t)idx] = siluf(acc);
}

__global__ void zero_kernel(float* __restrict__ p, int n)
{
    int i = blockIdx.x * blockDim.x + threadIdx.x;
    if (i < n) p[i] = 0.f;
}

// ---------------- chunked selective scan ----------------
__global__ void scan_phase1(const float* __restrict__ A_log)
{
    int idx = blockIdx.x * blockDim.x + threadIdx.x;
    int ed = idx & (ED - 1);
    int c  = (idx >> 11) & (NCH - 1);
    int b  = idx >> 15;

    float A2[NST];
#pragma unroll
    for (int n = 0; n < NST; n++)
        A2[n] = -__expf(A_log[ed * NST + n]) * 1.4426950408889634f;

    float h[NST];
#pragma unroll
    for (int n = 0; n < NST; n++) h[n] = 0.f;
    float sd = 0.f;

    int row0 = b * SEQLEN + c * CH;
    const float* dl = g_delta + (size_t)row0 * ED + ed;
    const float* xv = g_xc    + (size_t)row0 * ED + ed;

    for (int l = 0; l < CH; l++) {
        float d = dl[(size_t)l * ED];
        float x = xv[(size_t)l * ED];
        sd += d;
        float dx = d * x;
        const float4* bb = (const float4*)(g_dbc + (size_t)(row0 + l) * DBCW + DTR);
#pragma unroll
        for (int q = 0; q < 4; q++) {
            float4 bv = bb[q];
            float bw[4] = { bv.x, bv.y, bv.z, bv.w };
#pragma unroll
            for (int jj = 0; jj < 4; jj++) {
                int n = q * 4 + jj;
                float dA = ex2f(A2[n] * d);
                h[n] = fmaf(dA, h[n], bw[jj] * dx);
            }
        }
    }

    size_t ob = ((size_t)(b * ED + ed) * NCH + c) * NST;
#pragma unroll
    for (int n = 0; n < NST; n++) {
        g_hend [ob + n] = h[n];
        g_aprod[ob + n] = ex2f(A2[n] * sd);
    }
}

__global__ void scan_phase2()
{
    int tid = blockIdx.x * blockDim.x + threadIdx.x;
    int n = tid & (NST - 1);
    int e = tid >> 4;
    float h = 0.f;
#pragma unroll
    for (int c = 0; c < NCH; c++) {
        size_t idx = ((size_t)e * NCH + c) * NST + n;
        g_h0[idx] = h;
        h = fmaf(g_aprod[idx], h, g_hend[idx]);
    }
}

__global__ void scan_phase3(const float* __restrict__ A_log,
                            const float* __restrict__ D_param)
{
    int idx = blockIdx.x * blockDim.x + threadIdx.x;
    int ed = idx & (ED - 1);
    int c  = (idx >> 11) & (NCH - 1);
    int b  = idx >> 15;

    float A2[NST];
#pragma unroll
    for (int n = 0; n < NST; n++)
        A2[n] = -__expf(A_log[ed * NST + n]) * 1.4426950408889634f;

    size_t hb = ((size_t)(b * ED + ed) * NCH + c) * NST;
    float h[NST];
#pragma unroll
    for (int n = 0; n < NST; n++) h[n] = g_h0[hb + n];
    float Dv = D_param[ed];

    int row0 = b * SEQLEN + c * CH;
    const float* dl = g_delta + (size_t)row0 * ED + ed;
    const float* xv = g_xc    + (size_t)row0 * ED + ed;

    for (int l = 0; l < CH; l++) {
        float d = dl[(size_t)l * ED];
        float x = xv[(size_t)l * ED];
        float dx = d * x;
        float y = Dv * x;
        const float4* bb = (const float4*)(g_dbc + (size_t)(row0 + l) * DBCW + DTR);
        const float4* cc = (const float4*)(g_dbc + (size_t)(row0 + l) * DBCW + DTR + NST);
#pragma unroll
        for (int q = 0; q < 4; q++) {
            float4 bv = bb[q];
            float4 cv = cc[q];
            float bw[4] = { bv.x, bv.y, bv.z, bv.w };
            float cw[4] = { cv.x, cv.y, cv.z, cv.w };
#pragma unroll
            for (int jj = 0; jj < 4; jj++) {
                int n = q * 4 + jj;
                float dA = ex2f(A2[n] * d);
                h[n] = fmaf(dA, h[n], bw[jj] * dx);
                y = fmaf(h[n], cw[jj], y);
            }
        }
        float z = g_xz[(size_t)(row0 + l) * (2 * ED) + ED + ed];
        g_yz[(size_t)(row0 + l) * ED + ed] = y * siluf(z);
    }
}

// ---------------- launch ----------------
extern "C" void kernel_launch(void* const* d_in, const int* in_sizes, int n_in,
                              void* d_out, int out_size)
{
    const float* x          = (const float*)d_in[0];
    const float* in_proj_w  = (const float*)d_in[1];
    const float* conv_w     = (const float*)d_in[2];
    const float* conv_b     = (const float*)d_in[3];
    const float* x_proj_w   = (const float*)d_in[4];
    const float* dt_w       = (const float*)d_in[5];
    const float* dt_b       = (const float*)d_in[6];
    const float* A_log      = (const float*)d_in[7];
    const float* D_param    = (const float*)d_in[8];
    const float* out_proj_w = (const float*)d_in[9];
    float* out = (float*)d_out;

    float *p_xz, *p_xc, *p_dbc, *p_delta, *p_yz;
    cudaGetSymbolAddress((void**)&p_xz,    g_xz);
    cudaGetSymbolAddress((void**)&p_xc,    g_xc);
    cudaGetSymbolAddress((void**)&p_dbc,   g_dbc);
    cudaGetSymbolAddress((void**)&p_delta, g_delta);
    cudaGetSymbolAddress((void**)&p_yz,    g_yz);

    static int attr_set = 0;
    if (!attr_set) {
        cudaFuncSetAttribute(gemm_mma<0,0,0>, cudaFuncAttributeMaxDynamicSharedMemorySize, MM_SMEM);
        cudaFuncSetAttribute(gemm_mma<0,1,1>, cudaFuncAttributeMaxDynamicSharedMemorySize, MM_SMEM);
        cudaFuncSetAttribute(gemm_mma<1,0,0>, cudaFuncAttributeMaxDynamicSharedMemorySize, MM_SMEM);
        attr_set = 1;
    }

    // G1: xz = x @ in_proj_w^T   (4096 x 4096 x 1024)  [tf32 mma]
    gemm_mma<0,0,0><<<dim3(32, 32, 1), 256, MM_SMEM>>>(
        x, in_proj_w, p_xz, nullptr, ROWS, 2 * ED, DMODEL,
        DMODEL, DMODEL, 2 * ED, DMODEL);

    // depthwise causal conv + silu
    conv_silu_kernel<<<(ROWS * ED) / 256, 256>>>(conv_w, conv_b);

    // G2: dbc = xc @ x_proj_w^T  (4096 x 96 x 2048), split-K=4 atomics [tf32 mma]
    zero_kernel<<<(ROWS * DBCW + 255) / 256, 256>>>(p_dbc, ROWS * DBCW);
    gemm_mma<0,1,1><<<dim3(1, 32, 4), 256, MM_SMEM>>>(
        p_xc, x_proj_w, p_dbc, nullptr, ROWS, DBCW, ED,
        ED, ED, DBCW, ED / 4);

    // G3: delta = softplus(dbc[:, :64] @ dt_w^T + dt_b)  (4096 x 2048 x 64) [tf32 mma]
    gemm_mma<1,0,0><<<dim3(16, 32, 1), 256, MM_SMEM>>>(
        p_dbc, dt_w, p_delta, dt_b, ROWS, ED, DTR,
        DBCW, DTR, ED, DTR);

    // chunked selective scan
    scan_phase1<<<(BATCH * NCH * ED) / 128, 128>>>(A_log);
    scan_phase2<<<(BATCH * ED * NST) / 256, 256>>>();
    scan_phase3<<<(BATCH * NCH * ED) / 128, 128>>>(A_log, D_param);

    // G4: out = yz @ out_proj_w^T  (4096 x 1024 x 2048) [tf32 mma]
    gemm_mma<0,0,0><<<dim3(8, 32, 1), 256, MM_SMEM>>>(
        p_yz, out_proj_w, out, nullptr, ROWS, DMODEL, ED,
        ED, ED, DMODEL, ED);
}